// round 17
// baseline (speedup 1.0000x reference)
#include <cuda_runtime.h>

// Bilateral 5x5, sigma_color = sigma_space = 1.1, reflect pad, (16,3,512,512) f32.
//
// out = sum_k w_k*s_k*p_k / sum_k w_k*s_k,  w_k = exp(-a*diff^2), a = 1/(2*1.1^2);
// the reference's two normalizations cancel. exp(-a*u), u in [0,1], is a deg-2
// Chebyshev poly; the full 2D spatial weight (6 classes) is folded into per-
// class poly coefficient triples (uniform registers).
//
// R17: software-pipelined multi-tile CTA. Each CTA covers 128x64 as 4
// vertically-stacked 128x16 tiles; the next tile's 15 gmem loads are issued
// into registers at the START of the current tile's compute (~2300 cyc of
// fma work hides ~600 cyc LDG latency), so only tile 0's load phase is
// exposed. Body per tile = R16 (8 px/thread, LDS.128 rows, 4 chains,
// center-tap shortcut).

#define H 512
#define W 512
#define NPLANES 48

#define TILE_W 128
#define TILE_H 16
#define ITERS  4              // tiles per CTA (vertical)
#define BLK_X 32
#define BLK_Y 8
#define SM_W  132
#define SM_H  20

typedef unsigned long long u64;

__device__ __forceinline__ u64 pk(float lo, float hi) {
    u64 r; asm("mov.b64 %0, {%1, %2};" : "=l"(r) : "f"(lo), "f"(hi)); return r;
}
__device__ __forceinline__ u64 f2add(u64 a, u64 b) {
    u64 d; asm("add.rn.f32x2 %0, %1, %2;" : "=l"(d) : "l"(a), "l"(b)); return d;
}
__device__ __forceinline__ u64 f2sub(u64 a, u64 b) {
    u64 d; asm("sub.rn.f32x2 %0, %1, %2;" : "=l"(d) : "l"(a), "l"(b)); return d;
}
__device__ __forceinline__ u64 f2mul(u64 a, u64 b) {
    u64 d; asm("mul.rn.f32x2 %0, %1, %2;" : "=l"(d) : "l"(a), "l"(b)); return d;
}
__device__ __forceinline__ u64 f2fma(u64 a, u64 b, u64 c) {
    u64 d; asm("fma.rn.f32x2 %0, %1, %2, %3;" : "=l"(d) : "l"(a), "l"(b), "l"(c)); return d;
}
__device__ __forceinline__ void unpk(u64 q, float& lo, float& hi) {
    asm("mov.b64 {%0, %1}, %2;" : "=f"(lo), "=f"(hi) : "l"(q));
}

__device__ __forceinline__ int reflect_idx(int i, int n) {
    if (i < 0)  i = -i;
    if (i >= n) i = 2 * n - 2 - i;
    return i;
}

// coefficient triples s*{Q2, Q1, Q0}, Q = {0.06969310, -0.40757903, 0.99969391}
// s: 1, G1, G2, G1^2, G1*G2, G2^2 (G1=0.66151464, G2=0.19149516)
#define K0_2 0.06969310f
#define K0_1 -0.40757903f
#define K0_0 0.99969391f
#define K1_2 0.04610273f
#define K1_1 -0.26961989f
#define K1_0 0.66131215f
#define K2_2 0.01334589f
#define K2_1 -0.07804951f
#define K2_0 0.19143654f
#define K3_2 0.03049787f
#define K3_1 -0.17835732f
#define K3_0 0.43746767f
#define K4_2 0.00882849f
#define K4_1 -0.05163074f
#define K4_0 0.12663790f
#define K5_2 0.00255572f
#define K5_1 -0.01494609f
#define K5_0 0.03665918f

__global__ __launch_bounds__(BLK_X * BLK_Y, 4)
void bilateral_kernel(const float* __restrict__ in, float* __restrict__ out) {
    __shared__ __align__(16) float smA[SM_H][SM_W];
    __shared__ __align__(16) float smB[SM_H][SM_W];

    const int tx = threadIdx.x;
    const int ty = threadIdx.y;
    const int bx = blockIdx.x * TILE_W;
    const int byBase = blockIdx.y * (TILE_H * ITERS);
    const int pbase = blockIdx.z * (H * W);    // < 2^31, 32-bit safe
    const float* inp = in + pbase;

    const bool interior_x = (bx != 0) && (bx != (W - TILE_W));

    // ---- load one tile's 15 values into registers (division-free) ----
    #define LDG_TILE(BY, PF)                                            \
    {                                                                   \
        const int by_ = (BY);                                           \
        if (interior_x && (by_ != 0) && (by_ != (H - TILE_H))) {        \
            const float* src = inp + ((by_ - 2) * W + (bx - 2));        \
            _Pragma("unroll")                                           \
            for (int rr = 0; rr < 3; rr++) {                            \
                int r = ty + rr * BLK_Y;                                \
                if (r < SM_H) {                                         \
                    const float* sr = src + r * W;                      \
                    _Pragma("unroll")                                   \
                    for (int cc = 0; cc < 5; cc++) {                    \
                        int c = tx + cc * BLK_X;                        \
                        if (c < SM_W) PF[rr][cc] = sr[c];               \
                    }                                                   \
                }                                                       \
            }                                                           \
        } else {                                                        \
            _Pragma("unroll")                                           \
            for (int rr = 0; rr < 3; rr++) {                            \
                int r = ty + rr * BLK_Y;                                \
                if (r < SM_H) {                                         \
                    int gy = reflect_idx(by_ - 2 + r, H);               \
                    const float* sr = inp + gy * W;                     \
                    _Pragma("unroll")                                   \
                    for (int cc = 0; cc < 5; cc++) {                    \
                        int c = tx + cc * BLK_X;                        \
                        if (c < SM_W) {                                 \
                            int gx = reflect_idx(bx - 2 + c, W);        \
                            PF[rr][cc] = sr[gx];                        \
                        }                                               \
                    }                                                   \
                }                                                       \
            }                                                           \
        }                                                               \
    }

    #define STS_TILE(PF)                                                \
    {                                                                   \
        _Pragma("unroll")                                               \
        for (int rr = 0; rr < 3; rr++) {                                \
            int r = ty + rr * BLK_Y;                                    \
            if (r < SM_H) {                                             \
                _Pragma("unroll")                                       \
                for (int cc = 0; cc < 5; cc++) {                        \
                    int c = tx + cc * BLK_X;                            \
                    if (c < SM_W) {                                     \
                        float v = PF[rr][cc];                           \
                        smA[r][c] = v;                                  \
                        if (c > 0) smB[r][c - 1] = v;                   \
                    }                                                   \
                }                                                       \
            }                                                           \
        }                                                               \
    }

    float pf[3][5];
    LDG_TILE(byBase, pf)
    STS_TILE(pf)
    __syncthreads();

    // packed coefficient triples (thread-invariant -> uniform registers)
    const u64 C0q2 = pk(K0_2, K0_2), C0q1 = pk(K0_1, K0_1), C0q0 = pk(K0_0, K0_0);
    const u64 C1q2 = pk(K1_2, K1_2), C1q1 = pk(K1_1, K1_1), C1q0 = pk(K1_0, K1_0);
    const u64 C2q2 = pk(K2_2, K2_2), C2q1 = pk(K2_1, K2_1), C2q0 = pk(K2_0, K2_0);
    const u64 C3q2 = pk(K3_2, K3_2), C3q1 = pk(K3_1, K3_1), C3q0 = pk(K3_0, K3_0);
    const u64 C4q2 = pk(K4_2, K4_2), C4q1 = pk(K4_1, K4_1), C4q0 = pk(K4_0, K4_0);
    const u64 C5q2 = pk(K5_2, K5_2), C5q1 = pk(K5_1, K5_1), C5q0 = pk(K5_0, K5_0);

    const int col = 4 * tx;        // 16B-aligned smem base column
    const int rb  = 2 * ty;

    #pragma unroll
    for (int it = 0; it < ITERS; it++) {
        const int by = byBase + it * TILE_H;

        // prefetch NEXT tile into registers; LDG latency hides under compute
        if (it < ITERS - 1) {
            LDG_TILE(by + TILE_H, pf)
        }

        // ---- compute current tile from smem ----
        const u64 ctrA1 = *(const u64*)&smA[rb + 2][col + 2];
        const u64 ctrA2 = *(const u64*)&smA[rb + 2][col + 4];
        const u64 ctrB1 = *(const u64*)&smA[rb + 3][col + 2];
        const u64 ctrB2 = *(const u64*)&smA[rb + 3][col + 4];

        u64 nA1, dA1, nA2, dA2, nB1, dB1, nB2, dB2;

        #define ROWLOAD(r)                                              \
            const float* rA = &smA[rb + (r)][col];                      \
            const float* rB = &smB[rb + (r)][col];                      \
            ulonglong2 a0 = *(const ulonglong2*)(rA);                   \
            ulonglong2 a4 = *(const ulonglong2*)(rA + 4);               \
            ulonglong2 b0 = *(const ulonglong2*)(rB);                   \
            ulonglong2 b4 = *(const ulonglong2*)(rB + 4);               \
            u64 q0 = a0.x, q2 = a0.y, q4 = a4.x, q6 = a4.y;             \
            u64 q1 = b0.x, q3 = b0.y, q5 = b4.x;

        #define TAPACC(P, CTR, Kc, NUM, DEN)                \
        {                                                   \
            u64 dd = f2sub((P), (CTR));                     \
            u64 uu = f2mul(dd, dd);                         \
            u64 tt = f2fma(Kc##q2, uu, Kc##q1);             \
            u64 ww = f2fma(tt, uu, Kc##q0);                 \
            DEN = f2add(DEN, ww);                           \
            NUM = f2fma(ww, (P), NUM);                      \
        }
        #define TAPINIT(P, CTR, Kc, NUM, DEN)               \
        {                                                   \
            u64 dd = f2sub((P), (CTR));                     \
            u64 uu = f2mul(dd, dd);                         \
            u64 tt = f2fma(Kc##q2, uu, Kc##q1);             \
            u64 ww = f2fma(tt, uu, Kc##q0);                 \
            DEN = ww;                                       \
            NUM = f2mul(ww, (P));                           \
        }
        #define TAPCTR(CTR, NUM, DEN)                       \
        {                                                   \
            DEN = f2add(DEN, C0q0);                         \
            NUM = f2fma(C0q0, (CTR), NUM);                  \
        }

        #define ROW5_P1(CTR, NUM, DEN, Ka, Kb, Kc)          \
            TAPACC(q0, CTR, Ka, NUM, DEN)                   \
            TAPACC(q1, CTR, Kb, NUM, DEN)                   \
            TAPACC(q2, CTR, Kc, NUM, DEN)                   \
            TAPACC(q3, CTR, Kb, NUM, DEN)                   \
            TAPACC(q4, CTR, Ka, NUM, DEN)
        #define ROW5_P2(CTR, NUM, DEN, Ka, Kb, Kc)          \
            TAPACC(q2, CTR, Ka, NUM, DEN)                   \
            TAPACC(q3, CTR, Kb, NUM, DEN)                   \
            TAPACC(q4, CTR, Kc, NUM, DEN)                   \
            TAPACC(q5, CTR, Kb, NUM, DEN)                   \
            TAPACC(q6, CTR, Ka, NUM, DEN)
        #define ROW5C_P1(CTR, NUM, DEN)                     \
            TAPACC(q0, CTR, C2, NUM, DEN)                   \
            TAPACC(q1, CTR, C1, NUM, DEN)                   \
            TAPCTR(CTR, NUM, DEN)                           \
            TAPACC(q3, CTR, C1, NUM, DEN)                   \
            TAPACC(q4, CTR, C2, NUM, DEN)
        #define ROW5C_P2(CTR, NUM, DEN)                     \
            TAPACC(q2, CTR, C2, NUM, DEN)                   \
            TAPACC(q3, CTR, C1, NUM, DEN)                   \
            TAPCTR(CTR, NUM, DEN)                           \
            TAPACC(q5, CTR, C1, NUM, DEN)                   \
            TAPACC(q6, CTR, C2, NUM, DEN)
        #define ROW5I_P1(CTR, NUM, DEN, Ka, Kb, Kc)         \
            TAPINIT(q0, CTR, Ka, NUM, DEN)                  \
            TAPACC(q1, CTR, Kb, NUM, DEN)                   \
            TAPACC(q2, CTR, Kc, NUM, DEN)                   \
            TAPACC(q3, CTR, Kb, NUM, DEN)                   \
            TAPACC(q4, CTR, Ka, NUM, DEN)
        #define ROW5I_P2(CTR, NUM, DEN, Ka, Kb, Kc)         \
            TAPINIT(q2, CTR, Ka, NUM, DEN)                  \
            TAPACC(q3, CTR, Kb, NUM, DEN)                   \
            TAPACC(q4, CTR, Kc, NUM, DEN)                   \
            TAPACC(q5, CTR, Kb, NUM, DEN)                   \
            TAPACC(q6, CTR, Ka, NUM, DEN)

        {   // row 0: A only (dv=2) — init A chains
            ROWLOAD(0)
            ROW5I_P1(ctrA1, nA1, dA1, C5, C4, C2)
            ROW5I_P2(ctrA2, nA2, dA2, C5, C4, C2)
        }
        {   // row 1: A dv=1, B dv=2 (init B)
            ROWLOAD(1)
            ROW5_P1 (ctrA1, nA1, dA1, C4, C3, C1)
            ROW5_P2 (ctrA2, nA2, dA2, C4, C3, C1)
            ROW5I_P1(ctrB1, nB1, dB1, C5, C4, C2)
            ROW5I_P2(ctrB2, nB2, dB2, C5, C4, C2)
        }
        {   // row 2: A dv=0 (center shortcut), B dv=1
            ROWLOAD(2)
            ROW5C_P1(ctrA1, nA1, dA1)
            ROW5C_P2(ctrA2, nA2, dA2)
            ROW5_P1 (ctrB1, nB1, dB1, C4, C3, C1)
            ROW5_P2 (ctrB2, nB2, dB2, C4, C3, C1)
        }
        {   // row 3: A dv=1, B dv=0 (center shortcut)
            ROWLOAD(3)
            ROW5_P1 (ctrA1, nA1, dA1, C4, C3, C1)
            ROW5_P2 (ctrA2, nA2, dA2, C4, C3, C1)
            ROW5C_P1(ctrB1, nB1, dB1)
            ROW5C_P2(ctrB2, nB2, dB2)
        }
        {   // row 4: A dv=2, B dv=1
            ROWLOAD(4)
            ROW5_P1(ctrA1, nA1, dA1, C5, C4, C2)
            ROW5_P2(ctrA2, nA2, dA2, C5, C4, C2)
            ROW5_P1(ctrB1, nB1, dB1, C4, C3, C1)
            ROW5_P2(ctrB2, nB2, dB2, C4, C3, C1)
        }
        {   // row 5: B only (dv=2)
            ROWLOAD(5)
            ROW5_P1(ctrB1, nB1, dB1, C5, C4, C2)
            ROW5_P2(ctrB2, nB2, dB2, C5, C4, C2)
        }

        #undef ROW5_P1
        #undef ROW5_P2
        #undef ROW5C_P1
        #undef ROW5C_P2
        #undef ROW5I_P1
        #undef ROW5I_P2
        #undef TAPACC
        #undef TAPINIT
        #undef TAPCTR
        #undef ROWLOAD

        float x0, x1, y0, y1;
        float4 oA, oB;
        unpk(nA1, x0, x1); unpk(dA1, y0, y1);
        oA.x = __fdividef(x0, y0); oA.y = __fdividef(x1, y1);
        unpk(nA2, x0, x1); unpk(dA2, y0, y1);
        oA.z = __fdividef(x0, y0); oA.w = __fdividef(x1, y1);
        unpk(nB1, x0, x1); unpk(dB1, y0, y1);
        oB.x = __fdividef(x0, y0); oB.y = __fdividef(x1, y1);
        unpk(nB2, x0, x1); unpk(dB2, y0, y1);
        oB.z = __fdividef(x0, y0); oB.w = __fdividef(x1, y1);

        float* op = out + (pbase + (by + rb) * W + bx + col);
        *(float4*)op       = oA;    // 16B aligned: bx+4tx
        *(float4*)(op + W) = oB;

        // ---- rotate: publish prefetched tile to smem ----
        if (it < ITERS - 1) {
            __syncthreads();        // all reads of current tile done
            STS_TILE(pf)
            __syncthreads();        // new tile visible
        }
    }

    #undef LDG_TILE
    #undef STS_TILE
}

extern "C" void kernel_launch(void* const* d_in, const int* in_sizes, int n_in,
                              void* d_out, int out_size) {
    const float* x = (const float*)d_in[0];
    float* y = (float*)d_out;
    dim3 block(BLK_X, BLK_Y);
    dim3 grid(W / TILE_W, H / (TILE_H * ITERS), NPLANES);
    bilateral_kernel<<<grid, block>>>(x, y);
}